// round 5
// baseline (speedup 1.0000x reference)
#include <cuda_runtime.h>
#include <cuda_bf16.h>
#include <cstddef>

#define N_NODES 100000
#define N_EDGES 1600000
#define N_FEAT  128
#define H_CH    64
#define N_GRAPHS 4096

// ---------------------------------------------------------------------------
// Scratch (device globals; no allocation allowed)
// ---------------------------------------------------------------------------
__device__ float g_deg [N_NODES];
__device__ float g_dinv[N_NODES];
__device__ float g_coef[N_EDGES];                       // dinv[src]*dinv[dst]
__device__ float g_hw  [(size_t)N_NODES * H_CH];        // message operand (h@W, no bias)
__device__ float g_agg [(size_t)N_NODES * H_CH];        // aggregation accumulator
__device__ float g_hs  [(size_t)N_NODES * H_CH];        // skip-path result
__device__ float g_pool[(size_t)N_GRAPHS * H_CH];
__device__ float g_cnt [N_GRAPHS];

// ---------------------------------------------------------------------------
// Small utility kernels
// ---------------------------------------------------------------------------
__global__ void zero_kernel(float* __restrict__ p, int n) {
    int i = blockIdx.x * blockDim.x + threadIdx.x;
    if (i < n) p[i] = 0.f;
}

__global__ void deg_kernel(const int* __restrict__ dst) {
    int i = blockIdx.x * blockDim.x + threadIdx.x;
    if (i < N_EDGES) atomicAdd(&g_deg[dst[i]], 1.0f);
}

__global__ void dinv_kernel() {
    int i = blockIdx.x * blockDim.x + threadIdx.x;
    if (i < N_NODES) g_dinv[i] = rsqrtf(g_deg[i] + 1.0f);
}

__global__ void coef_kernel(const int* __restrict__ src, const int* __restrict__ dst) {
    int i = blockIdx.x * blockDim.x + threadIdx.x;
    if (i < N_EDGES) g_coef[i] = g_dinv[src[i]] * g_dinv[dst[i]];
}

// ---------------------------------------------------------------------------
// Layer-0 GEMM:  raw[N,64] = X[N,128] @ W[128,64]
// Epilogue: g_hw = raw;  g_agg = raw * dinv[n]^2 + bias  (agg initialized here)
// Block: 256 threads, 128 nodes/block, each thread: 4 nodes x 8 outputs.
// ---------------------------------------------------------------------------
__global__ void __launch_bounds__(256)
gemm0_kernel(const float* __restrict__ X, const float* __restrict__ W,
             const float* __restrict__ bias) {
    const int K = 128;
    extern __shared__ float sm[];
    float* Ws = sm;                // 128*64
    float* Xs = sm + K * 64;       // 128*129 (padded)

    const int tid = threadIdx.x;
    const int n0  = blockIdx.x * 128;

    for (int i = tid; i < K * 64 / 4; i += 256)
        *(float4*)&Ws[i * 4] = *(const float4*)&W[i * 4];
    for (int i = tid; i < 128 * K / 4; i += 256) {   // float4-vectorized tile load
        int r = i / (K / 4), c4 = i - r * (K / 4);
        int n = n0 + r;
        float4 xv = make_float4(0.f, 0.f, 0.f, 0.f);
        if (n < N_NODES) xv = *(const float4*)&X[(size_t)n * K + c4 * 4];
        float* xp = &Xs[r * (K + 1) + c4 * 4];
        xp[0] = xv.x; xp[1] = xv.y; xp[2] = xv.z; xp[3] = xv.w;
    }
    __syncthreads();

    const int lane = tid & 31;
    const int warp = tid >> 5;
    const int og   = warp * 8;

    float acc[4][8];
#pragma unroll
    for (int r = 0; r < 4; r++)
#pragma unroll
        for (int j = 0; j < 8; j++) acc[r][j] = 0.f;

    const float* xr0 = &Xs[(lane +  0) * (K + 1)];
    const float* xr1 = &Xs[(lane + 32) * (K + 1)];
    const float* xr2 = &Xs[(lane + 64) * (K + 1)];
    const float* xr3 = &Xs[(lane + 96) * (K + 1)];

#pragma unroll 4
    for (int k = 0; k < K; k++) {
        const float4 wa = *(const float4*)&Ws[k * 64 + og];
        const float4 wb = *(const float4*)&Ws[k * 64 + og + 4];
        float xv;
#define DO_ROW(r, xp)                                                        \
        xv = xp[k];                                                          \
        acc[r][0] += xv * wa.x; acc[r][1] += xv * wa.y;                      \
        acc[r][2] += xv * wa.z; acc[r][3] += xv * wa.w;                      \
        acc[r][4] += xv * wb.x; acc[r][5] += xv * wb.y;                      \
        acc[r][6] += xv * wb.z; acc[r][7] += xv * wb.w;
        DO_ROW(0, xr0) DO_ROW(1, xr1) DO_ROW(2, xr2) DO_ROW(3, xr3)
#undef DO_ROW
    }

    const float4 ba = *(const float4*)&bias[og];
    const float4 bb = *(const float4*)&bias[og + 4];

#pragma unroll
    for (int r = 0; r < 4; r++) {
        int n = n0 + lane + 32 * r;
        if (n >= N_NODES) continue;
        float d  = g_dinv[n];
        float d2 = d * d;
        float* op = g_hw  + (size_t)n * 64 + og;
        float* ap = g_agg + (size_t)n * 64 + og;
        float4 o0 = make_float4(acc[r][0], acc[r][1], acc[r][2], acc[r][3]);
        float4 o1 = make_float4(acc[r][4], acc[r][5], acc[r][6], acc[r][7]);
        *(float4*)op       = o0;
        *(float4*)(op + 4) = o1;
        *(float4*)ap       = make_float4(fmaf(o0.x, d2, ba.x), fmaf(o0.y, d2, ba.y),
                                         fmaf(o0.z, d2, ba.z), fmaf(o0.w, d2, ba.w));
        *(float4*)(ap + 4) = make_float4(fmaf(o1.x, d2, bb.x), fmaf(o1.y, d2, bb.y),
                                         fmaf(o1.z, d2, bb.z), fmaf(o1.w, d2, bb.w));
    }
}

// ---------------------------------------------------------------------------
// Fused dual GEMM for layers 1.. : input h is NOT materialized; the loader
// computes it from the previous layer's buffers:
//   MODE 0 (after layer0):  x = relu(agg)
//   MODE 1 (after layer1+): x = relu(agg) + hs
// One pass computes BOTH:
//   conv: raw = x @ Wc;  g_hw = raw;  g_agg = raw*dinv^2 + bc   (overwrites agg)
//   skip: g_hs = x @ Wsk + bs                                   (overwrites hs)
// Safe: each block reads exactly the rows it later writes (disjoint blocks),
// and reads complete (syncthreads) before the epilogue writes.
// ---------------------------------------------------------------------------
template <int MODE>
__global__ void __launch_bounds__(256)
gemm_dual_kernel(const float* __restrict__ Wc, const float* __restrict__ bc,
                 const float* __restrict__ Wsk, const float* __restrict__ bs) {
    const int K = 64;
    extern __shared__ float sm[];
    float* Wcs = sm;                    // 64*64
    float* Wss = sm + K * 64;           // 64*64
    float* Xs  = sm + 2 * K * 64;       // 128*65

    const int tid = threadIdx.x;
    const int n0  = blockIdx.x * 128;

    for (int i = tid; i < K * 64 / 4; i += 256) {
        *(float4*)&Wcs[i * 4] = *(const float4*)&Wc[i * 4];
        *(float4*)&Wss[i * 4] = *(const float4*)&Wsk[i * 4];
    }
    for (int i = tid; i < 128 * K / 4; i += 256) {   // float4-vectorized tile load
        int r = i / (K / 4), c4 = i - r * (K / 4);
        int n = n0 + r;
        float4 xv = make_float4(0.f, 0.f, 0.f, 0.f);
        if (n < N_NODES) {
            float4 a = *(const float4*)&g_agg[(size_t)n * K + c4 * 4];
            xv = make_float4(fmaxf(a.x, 0.f), fmaxf(a.y, 0.f),
                             fmaxf(a.z, 0.f), fmaxf(a.w, 0.f));
            if (MODE == 1) {
                float4 s = *(const float4*)&g_hs[(size_t)n * K + c4 * 4];
                xv.x += s.x; xv.y += s.y; xv.z += s.z; xv.w += s.w;
            }
        }
        float* xp = &Xs[r * (K + 1) + c4 * 4];
        xp[0] = xv.x; xp[1] = xv.y; xp[2] = xv.z; xp[3] = xv.w;
    }
    __syncthreads();

    const int lane = tid & 31;
    const int warp = tid >> 5;
    const int og   = warp * 8;

    float accC[4][8], accS[4][8];
#pragma unroll
    for (int r = 0; r < 4; r++)
#pragma unroll
        for (int j = 0; j < 8; j++) { accC[r][j] = 0.f; accS[r][j] = 0.f; }

    const float* xr0 = &Xs[(lane +  0) * (K + 1)];
    const float* xr1 = &Xs[(lane + 32) * (K + 1)];
    const float* xr2 = &Xs[(lane + 64) * (K + 1)];
    const float* xr3 = &Xs[(lane + 96) * (K + 1)];

#pragma unroll 2
    for (int k = 0; k < K; k++) {
        const float4 ca = *(const float4*)&Wcs[k * 64 + og];
        const float4 cb = *(const float4*)&Wcs[k * 64 + og + 4];
        const float4 sa = *(const float4*)&Wss[k * 64 + og];
        const float4 sb = *(const float4*)&Wss[k * 64 + og + 4];
        float xv;
#define DO_ROW(r, xp)                                                          \
        xv = xp[k];                                                            \
        accC[r][0] += xv * ca.x; accC[r][1] += xv * ca.y;                      \
        accC[r][2] += xv * ca.z; accC[r][3] += xv * ca.w;                      \
        accC[r][4] += xv * cb.x; accC[r][5] += xv * cb.y;                      \
        accC[r][6] += xv * cb.z; accC[r][7] += xv * cb.w;                      \
        accS[r][0] += xv * sa.x; accS[r][1] += xv * sa.y;                      \
        accS[r][2] += xv * sa.z; accS[r][3] += xv * sa.w;                      \
        accS[r][4] += xv * sb.x; accS[r][5] += xv * sb.y;                      \
        accS[r][6] += xv * sb.z; accS[r][7] += xv * sb.w;
        DO_ROW(0, xr0) DO_ROW(1, xr1) DO_ROW(2, xr2) DO_ROW(3, xr3)
#undef DO_ROW
    }

    const float4 bca = *(const float4*)&bc[og];
    const float4 bcb = *(const float4*)&bc[og + 4];
    const float4 bsa = *(const float4*)&bs[og];
    const float4 bsb = *(const float4*)&bs[og + 4];

#pragma unroll
    for (int r = 0; r < 4; r++) {
        int n = n0 + lane + 32 * r;
        if (n >= N_NODES) continue;
        float d  = g_dinv[n];
        float d2 = d * d;
        float* op = g_hw  + (size_t)n * 64 + og;
        float* ap = g_agg + (size_t)n * 64 + og;
        float* sp = g_hs  + (size_t)n * 64 + og;
        float4 o0 = make_float4(accC[r][0], accC[r][1], accC[r][2], accC[r][3]);
        float4 o1 = make_float4(accC[r][4], accC[r][5], accC[r][6], accC[r][7]);
        *(float4*)op       = o0;
        *(float4*)(op + 4) = o1;
        *(float4*)ap       = make_float4(fmaf(o0.x, d2, bca.x), fmaf(o0.y, d2, bca.y),
                                         fmaf(o0.z, d2, bca.z), fmaf(o0.w, d2, bca.w));
        *(float4*)(ap + 4) = make_float4(fmaf(o1.x, d2, bcb.x), fmaf(o1.y, d2, bcb.y),
                                         fmaf(o1.z, d2, bcb.z), fmaf(o1.w, d2, bcb.w));
        *(float4*)sp       = make_float4(accS[r][0] + bsa.x, accS[r][1] + bsa.y,
                                         accS[r][2] + bsa.z, accS[r][3] + bsa.w);
        *(float4*)(sp + 4) = make_float4(accS[r][4] + bsb.x, accS[r][5] + bsb.y,
                                         accS[r][6] + bsb.z, accS[r][7] + bsb.w);
    }
}

// ---------------------------------------------------------------------------
// Edge aggregation: agg[dst] += hw[src] * coef[e]
// 8 threads per edge; each handles two float4 chunks (q and q+32 floats).
// red.global.add.v4.f32: no-return L2-side reduction.
// ---------------------------------------------------------------------------
__global__ void __launch_bounds__(256) edge_kernel(const int* __restrict__ src,
                                                   const int* __restrict__ dst) {
    int gid = blockIdx.x * blockDim.x + threadIdx.x;
    int e = gid >> 3;
    if (e >= N_EDGES) return;
    // front-batch the scalar loads so they overlap the gather latency
    const int   s = __ldg(&src[e]);
    const int   d = __ldg(&dst[e]);
    const float c = __ldg(&g_coef[e]);
    const int q = (gid & 7) << 2;              // 0,4,...,28
    const float* hp = &g_hw[(size_t)s * 64 + q];
    float* ap = &g_agg[(size_t)d * 64 + q];
    float4 v0 = __ldg((const float4*)hp);
    float4 v1 = __ldg((const float4*)(hp + 32));
    asm volatile("red.global.add.v4.f32 [%0], {%1, %2, %3, %4};"
                 :: "l"(ap), "f"(v0.x * c), "f"(v0.y * c), "f"(v0.z * c), "f"(v0.w * c)
                 : "memory");
    asm volatile("red.global.add.v4.f32 [%0], {%1, %2, %3, %4};"
                 :: "l"(ap + 32), "f"(v1.x * c), "f"(v1.y * c), "f"(v1.z * c), "f"(v1.w * c)
                 : "memory");
}

// global mean-pool accumulation; input h = relu(agg) + hs computed on the fly
__global__ void pool_kernel(const int* __restrict__ b) {
    int gid = blockIdx.x * blockDim.x + threadIdx.x;
    int n = gid >> 4;
    if (n >= N_NODES) return;
    int q = (gid & 15) << 2;
    int g = __ldg(&b[n]);
    float4 a = __ldg((const float4*)&g_agg[(size_t)n * 64 + q]);
    float4 s = __ldg((const float4*)&g_hs[(size_t)n * 64 + q]);
    float4 v = make_float4(fmaxf(a.x, 0.f) + s.x, fmaxf(a.y, 0.f) + s.y,
                           fmaxf(a.z, 0.f) + s.z, fmaxf(a.w, 0.f) + s.w);
    float* p = &g_pool[(size_t)g * 64 + q];
    asm volatile("red.global.add.v4.f32 [%0], {%1, %2, %3, %4};"
                 :: "l"(p), "f"(v.x), "f"(v.y), "f"(v.z), "f"(v.w) : "memory");
    if (q == 0) atomicAdd(&g_cnt[g], 1.0f);
}

// MLP head: one warp per graph
__global__ void head_kernel(const float* __restrict__ lin1W, const float* __restrict__ lin1b,
                            const float* __restrict__ lin2W, const float* __restrict__ lin2b,
                            float* __restrict__ outp) {
    int gid  = blockIdx.x * blockDim.x + threadIdx.x;
    int g    = gid >> 5;
    int lane = gid & 31;
    if (g >= N_GRAPHS) return;
    float rc = 1.0f / fmaxf(g_cnt[g], 1.0f);
    float acc = 0.f;
#pragma unroll
    for (int k = 0; k < 64; k++)
        acc += g_pool[(size_t)g * 64 + k] * lin1W[k * 32 + lane];
    acc = fmaxf(fmaf(acc, rc, lin1b[lane]), 0.f);
    float part = acc * lin2W[lane];
#pragma unroll
    for (int off = 16; off; off >>= 1)
        part += __shfl_down_sync(0xffffffffu, part, off);
    if (lane == 0) outp[g] = part + lin2b[0];
}

// ---------------------------------------------------------------------------
extern "C" void kernel_launch(void* const* d_in, const int* in_sizes, int n_in,
                              void* d_out, int out_size) {
    const float* x     = (const float*)d_in[0];
    const int*   e_idx = (const int*)  d_in[1];
    const int*   src   = e_idx;
    const int*   dst   = e_idx + N_EDGES;
    const int*   b     = (const int*)  d_in[2];
    const float* w0    = (const float*)d_in[3];
    const float* b0    = (const float*)d_in[4];
    const float* convW = (const float*)d_in[5];
    const float* convB = (const float*)d_in[6];
    const float* skipW = (const float*)d_in[7];
    const float* skipB = (const float*)d_in[8];
    const float* lin1W = (const float*)d_in[9];
    const float* lin1b = (const float*)d_in[10];
    const float* lin2W = (const float*)d_in[11];
    const float* lin2b = (const float*)d_in[12];
    float* out = (float*)d_out;

    float *deg, *pool, *cnt;
    cudaGetSymbolAddress((void**)&deg,  g_deg);
    cudaGetSymbolAddress((void**)&pool, g_pool);
    cudaGetSymbolAddress((void**)&cnt,  g_cnt);

    const int SMEM0 = (128 * 64 + 128 * 129) * 4;   // 98816 B
    const int SMEMD = (2 * 64 * 64 + 128 * 65) * 4; // 66048 B
    cudaFuncSetAttribute(gemm0_kernel, cudaFuncAttributeMaxDynamicSharedMemorySize, SMEM0);
    cudaFuncSetAttribute(gemm_dual_kernel<0>, cudaFuncAttributeMaxDynamicSharedMemorySize, SMEMD);
    cudaFuncSetAttribute(gemm_dual_kernel<1>, cudaFuncAttributeMaxDynamicSharedMemorySize, SMEMD);

    const int NB_NODE  = (N_NODES + 255) / 256;
    const int NB_GEMM  = (N_NODES + 127) / 128;        // 782
    const int NB_EDGEV = (N_EDGES * 8 + 255) / 256;    // 50000
    const int NB_HV    = (N_NODES * 16 + 255) / 256;   // 6250
    const int NB_EDGE  = (N_EDGES + 255) / 256;

    // degree + normalization + per-edge coefficients (layer-invariant)
    zero_kernel<<<NB_NODE, 256>>>(deg, N_NODES);
    deg_kernel<<<NB_EDGE, 256>>>(dst);
    dinv_kernel<<<NB_NODE, 256>>>();
    coef_kernel<<<NB_EDGE, 256>>>(src, dst);

    // layer 0: agg0 = GCNConv(x, w0, b0)
    gemm0_kernel<<<NB_GEMM, 256, SMEM0>>>(x, w0, b0);
    edge_kernel<<<NB_EDGEV, 256>>>(src, dst);

    // layer 1: x1 = relu(agg0); conv+skip fused GEMM, then edge pass
    gemm_dual_kernel<0><<<NB_GEMM, 256, SMEMD>>>(convW, convB, skipW, skipB);
    edge_kernel<<<NB_EDGEV, 256>>>(src, dst);

    // layer 2: x2 = relu(agg1) + hs1; conv+skip fused GEMM, then edge pass
    gemm_dual_kernel<1><<<NB_GEMM, 256, SMEMD>>>(convW + 64 * 64, convB + 64,
                                                 skipW + 64 * 64, skipB + 64);
    edge_kernel<<<NB_EDGEV, 256>>>(src, dst);

    // global mean pool (h = relu(agg2) + hs2 on the fly) + MLP head
    zero_kernel<<<(N_GRAPHS * 64 + 255) / 256, 256>>>(pool, N_GRAPHS * 64);
    zero_kernel<<<(N_GRAPHS + 255) / 256, 256>>>(cnt, N_GRAPHS);
    pool_kernel<<<NB_HV, 256>>>(b);
    head_kernel<<<(N_GRAPHS * 32 + 255) / 256, 256>>>(lin1W, lin1b, lin2W, lin2b, out);
}

// round 7
// speedup vs baseline: 1.0394x; 1.0394x over previous
#include <cuda_runtime.h>
#include <cuda_bf16.h>
#include <cstddef>

#define N_NODES 100000
#define N_EDGES 1600000
#define N_FEAT  128
#define H_CH    64
#define N_GRAPHS 4096

// ---------------------------------------------------------------------------
// Scratch (device globals; no allocation allowed)
// ---------------------------------------------------------------------------
__device__ float g_deg [N_NODES];
__device__ float g_dinv[N_NODES];
__device__ float g_hw  [(size_t)N_NODES * H_CH];   // pre-scaled message: (h@W)*dinv[n]
__device__ float g_agg [(size_t)N_NODES * H_CH];   // pre-scale-domain accumulator
__device__ float g_hs  [(size_t)N_NODES * H_CH];   // skip-path result
__device__ float g_pool[(size_t)N_GRAPHS * H_CH];
__device__ float g_cnt [N_GRAPHS];

// ---------------------------------------------------------------------------
// Small utility kernels
// ---------------------------------------------------------------------------
__global__ void zero_kernel(float* __restrict__ p, int n) {
    int i = blockIdx.x * blockDim.x + threadIdx.x;
    if (i < n) p[i] = 0.f;
}

__global__ void deg_kernel(const int* __restrict__ dst) {
    int i = blockIdx.x * blockDim.x + threadIdx.x;
    if (i < N_EDGES) atomicAdd(&g_deg[dst[i]], 1.0f);
}

__global__ void dinv_kernel() {
    int i = blockIdx.x * blockDim.x + threadIdx.x;
    if (i < N_NODES) g_dinv[i] = rsqrtf(g_deg[i] + 1.0f);
}

// ---------------------------------------------------------------------------
// Layer-0 GEMM:  raw[N,64] = X[N,128] @ W[128,64]
// Epilogue (pre-scale domain): hwS = raw * dinv[n];  agg = hwS  (self-term).
// Consumer applies  out = agg * dinv[n] + bias  later.
// Block: 256 threads, 128 nodes/block, each thread: 4 nodes x 8 outputs.
// ---------------------------------------------------------------------------
__global__ void __launch_bounds__(256)
gemm0_kernel(const float* __restrict__ X, const float* __restrict__ W) {
    const int K = 128;
    extern __shared__ float sm[];
    float* Ws = sm;                // 128*64
    float* Xs = sm + K * 64;       // 128*129 (padded)

    const int tid = threadIdx.x;
    const int n0  = blockIdx.x * 128;

    for (int i = tid; i < K * 64 / 4; i += 256)
        *(float4*)&Ws[i * 4] = *(const float4*)&W[i * 4];
    for (int i = tid; i < 128 * K / 4; i += 256) {   // float4-vectorized tile load
        int r = i / (K / 4), c4 = i - r * (K / 4);
        int n = n0 + r;
        float4 xv = make_float4(0.f, 0.f, 0.f, 0.f);
        if (n < N_NODES) xv = *(const float4*)&X[(size_t)n * K + c4 * 4];
        float* xp = &Xs[r * (K + 1) + c4 * 4];
        xp[0] = xv.x; xp[1] = xv.y; xp[2] = xv.z; xp[3] = xv.w;
    }
    __syncthreads();

    const int lane = tid & 31;
    const int warp = tid >> 5;
    const int og   = warp * 8;

    float acc[4][8];
#pragma unroll
    for (int r = 0; r < 4; r++)
#pragma unroll
        for (int j = 0; j < 8; j++) acc[r][j] = 0.f;

    const float* xr0 = &Xs[(lane +  0) * (K + 1)];
    const float* xr1 = &Xs[(lane + 32) * (K + 1)];
    const float* xr2 = &Xs[(lane + 64) * (K + 1)];
    const float* xr3 = &Xs[(lane + 96) * (K + 1)];

#pragma unroll 4
    for (int k = 0; k < K; k++) {
        const float4 wa = *(const float4*)&Ws[k * 64 + og];
        const float4 wb = *(const float4*)&Ws[k * 64 + og + 4];
        float xv;
#define DO_ROW(r, xp)                                                        \
        xv = xp[k];                                                          \
        acc[r][0] += xv * wa.x; acc[r][1] += xv * wa.y;                      \
        acc[r][2] += xv * wa.z; acc[r][3] += xv * wa.w;                      \
        acc[r][4] += xv * wb.x; acc[r][5] += xv * wb.y;                      \
        acc[r][6] += xv * wb.z; acc[r][7] += xv * wb.w;
        DO_ROW(0, xr0) DO_ROW(1, xr1) DO_ROW(2, xr2) DO_ROW(3, xr3)
#undef DO_ROW
    }

#pragma unroll
    for (int r = 0; r < 4; r++) {
        int n = n0 + lane + 32 * r;
        if (n >= N_NODES) continue;
        float dn = g_dinv[n];
        float* op = g_hw  + (size_t)n * 64 + og;
        float* ap = g_agg + (size_t)n * 64 + og;
        float4 o0 = make_float4(acc[r][0] * dn, acc[r][1] * dn, acc[r][2] * dn, acc[r][3] * dn);
        float4 o1 = make_float4(acc[r][4] * dn, acc[r][5] * dn, acc[r][6] * dn, acc[r][7] * dn);
        *(float4*)op       = o0;
        *(float4*)(op + 4) = o1;
        *(float4*)ap       = o0;        // self-term init (pre-scale domain)
        *(float4*)(ap + 4) = o1;
    }
}

// ---------------------------------------------------------------------------
// Fused dual GEMM for layers 1.. : input h computed on the fly from the
// previous layer's pre-scale-domain agg:
//   MODE 0:  x = relu(agg*dinv[n] + bias_prev)
//   MODE 1:  x = relu(agg*dinv[n] + bias_prev) + hs
// One pass computes BOTH:
//   conv: raw = x @ Wc;  hwS = raw*dinv;  agg = hwS     (overwrites agg)
//   skip: g_hs = x @ Wsk + bs                           (overwrites hs)
// Safe: each block reads exactly the rows it later writes (disjoint blocks),
// and reads complete (syncthreads) before the epilogue writes.
// ---------------------------------------------------------------------------
template <int MODE>
__global__ void __launch_bounds__(256)
gemm_dual_kernel(const float* __restrict__ Wc, const float* __restrict__ bias_prev,
                 const float* __restrict__ Wsk, const float* __restrict__ bs) {
    const int K = 64;
    extern __shared__ float sm[];
    float* Wcs = sm;                    // 64*64
    float* Wss = sm + K * 64;           // 64*64
    float* Xs  = sm + 2 * K * 64;       // 128*65

    const int tid = threadIdx.x;
    const int n0  = blockIdx.x * 128;

    for (int i = tid; i < K * 64 / 4; i += 256) {
        *(float4*)&Wcs[i * 4] = *(const float4*)&Wc[i * 4];
        *(float4*)&Wss[i * 4] = *(const float4*)&Wsk[i * 4];
    }
    for (int i = tid; i < 128 * K / 4; i += 256) {   // float4-vectorized tile load
        int r = i / (K / 4), c4 = i - r * (K / 4);
        int n = n0 + r;
        float4 xv = make_float4(0.f, 0.f, 0.f, 0.f);
        if (n < N_NODES) {
            float dn = g_dinv[n];
            float4 bb = *(const float4*)&bias_prev[c4 * 4];
            float4 a = *(const float4*)&g_agg[(size_t)n * K + c4 * 4];
            xv = make_float4(fmaxf(fmaf(a.x, dn, bb.x), 0.f),
                             fmaxf(fmaf(a.y, dn, bb.y), 0.f),
                             fmaxf(fmaf(a.z, dn, bb.z), 0.f),
                             fmaxf(fmaf(a.w, dn, bb.w), 0.f));
            if (MODE == 1) {
                float4 s = *(const float4*)&g_hs[(size_t)n * K + c4 * 4];
                xv.x += s.x; xv.y += s.y; xv.z += s.z; xv.w += s.w;
            }
        }
        float* xp = &Xs[r * (K + 1) + c4 * 4];
        xp[0] = xv.x; xp[1] = xv.y; xp[2] = xv.z; xp[3] = xv.w;
    }
    __syncthreads();

    const int lane = tid & 31;
    const int warp = tid >> 5;
    const int og   = warp * 8;

    float accC[4][8], accS[4][8];
#pragma unroll
    for (int r = 0; r < 4; r++)
#pragma unroll
        for (int j = 0; j < 8; j++) { accC[r][j] = 0.f; accS[r][j] = 0.f; }

    const float* xr0 = &Xs[(lane +  0) * (K + 1)];
    const float* xr1 = &Xs[(lane + 32) * (K + 1)];
    const float* xr2 = &Xs[(lane + 64) * (K + 1)];
    const float* xr3 = &Xs[(lane + 96) * (K + 1)];

#pragma unroll 2
    for (int k = 0; k < K; k++) {
        const float4 ca = *(const float4*)&Wcs[k * 64 + og];
        const float4 cb = *(const float4*)&Wcs[k * 64 + og + 4];
        const float4 sa = *(const float4*)&Wss[k * 64 + og];
        const float4 sb = *(const float4*)&Wss[k * 64 + og + 4];
        float xv;
#define DO_ROW(r, xp)                                                          \
        xv = xp[k];                                                            \
        accC[r][0] += xv * ca.x; accC[r][1] += xv * ca.y;                      \
        accC[r][2] += xv * ca.z; accC[r][3] += xv * ca.w;                      \
        accC[r][4] += xv * cb.x; accC[r][5] += xv * cb.y;                      \
        accC[r][6] += xv * cb.z; accC[r][7] += xv * cb.w;                      \
        accS[r][0] += xv * sa.x; accS[r][1] += xv * sa.y;                      \
        accS[r][2] += xv * sa.z; accS[r][3] += xv * sa.w;                      \
        accS[r][4] += xv * sb.x; accS[r][5] += xv * sb.y;                      \
        accS[r][6] += xv * sb.z; accS[r][7] += xv * sb.w;
        DO_ROW(0, xr0) DO_ROW(1, xr1) DO_ROW(2, xr2) DO_ROW(3, xr3)
#undef DO_ROW
    }

    const float4 bsa = *(const float4*)&bs[og];
    const float4 bsb = *(const float4*)&bs[og + 4];

#pragma unroll
    for (int r = 0; r < 4; r++) {
        int n = n0 + lane + 32 * r;
        if (n >= N_NODES) continue;
        float dn = g_dinv[n];
        float* op = g_hw  + (size_t)n * 64 + og;
        float* ap = g_agg + (size_t)n * 64 + og;
        float* sp = g_hs  + (size_t)n * 64 + og;
        float4 o0 = make_float4(accC[r][0] * dn, accC[r][1] * dn, accC[r][2] * dn, accC[r][3] * dn);
        float4 o1 = make_float4(accC[r][4] * dn, accC[r][5] * dn, accC[r][6] * dn, accC[r][7] * dn);
        *(float4*)op       = o0;
        *(float4*)(op + 4) = o1;
        *(float4*)ap       = o0;        // self-term init (pre-scale domain)
        *(float4*)(ap + 4) = o1;
        *(float4*)sp       = make_float4(accS[r][0] + bsa.x, accS[r][1] + bsa.y,
                                         accS[r][2] + bsa.z, accS[r][3] + bsa.w);
        *(float4*)(sp + 4) = make_float4(accS[r][4] + bsb.x, accS[r][5] + bsb.y,
                                         accS[r][6] + bsb.z, accS[r][7] + bsb.w);
    }
}

// ---------------------------------------------------------------------------
// Edge aggregation (pre-scale domain): agg[dst] += hwS[src]
// No coefficient: normalization folded into producer/consumer.
// 8 threads per edge; each handles two float4 chunks.
// ---------------------------------------------------------------------------
__global__ void __launch_bounds__(256) edge_kernel(const int* __restrict__ src,
                                                   const int* __restrict__ dst) {
    int gid = blockIdx.x * blockDim.x + threadIdx.x;
    int e = gid >> 3;
    if (e >= N_EDGES) return;
    const int s = __ldg(&src[e]);
    const int d = __ldg(&dst[e]);
    const int q = (gid & 7) << 2;              // 0,4,...,28
    const float* hp = &g_hw[(size_t)s * 64 + q];
    float* ap = &g_agg[(size_t)d * 64 + q];
    float4 v0 = __ldg((const float4*)hp);
    float4 v1 = __ldg((const float4*)(hp + 32));
    asm volatile("red.global.add.v4.f32 [%0], {%1, %2, %3, %4};"
                 :: "l"(ap), "f"(v0.x), "f"(v0.y), "f"(v0.z), "f"(v0.w) : "memory");
    asm volatile("red.global.add.v4.f32 [%0], {%1, %2, %3, %4};"
                 :: "l"(ap + 32), "f"(v1.x), "f"(v1.y), "f"(v1.z), "f"(v1.w) : "memory");
}

// global mean-pool accumulation; h = relu(agg*dinv + bias2) + hs on the fly
__global__ void pool_kernel(const int* __restrict__ b, const float* __restrict__ bias2) {
    int gid = blockIdx.x * blockDim.x + threadIdx.x;
    int n = gid >> 4;
    if (n >= N_NODES) return;
    int q = (gid & 15) << 2;
    int g = __ldg(&b[n]);
    float dn = __ldg(&g_dinv[n]);
    float4 bb = *(const float4*)&bias2[q];
    float4 a = __ldg((const float4*)&g_agg[(size_t)n * 64 + q]);
    float4 s = __ldg((const float4*)&g_hs[(size_t)n * 64 + q]);
    float4 v = make_float4(fmaxf(fmaf(a.x, dn, bb.x), 0.f) + s.x,
                           fmaxf(fmaf(a.y, dn, bb.y), 0.f) + s.y,
                           fmaxf(fmaf(a.z, dn, bb.z), 0.f) + s.z,
                           fmaxf(fmaf(a.w, dn, bb.w), 0.f) + s.w);
    float* p = &g_pool[(size_t)g * 64 + q];
    asm volatile("red.global.add.v4.f32 [%0], {%1, %2, %3, %4};"
                 :: "l"(p), "f"(v.x), "f"(v.y), "f"(v.z), "f"(v.w) : "memory");
    if (q == 0) atomicAdd(&g_cnt[g], 1.0f);
}

// MLP head: one warp per graph
__global__ void head_kernel(const float* __restrict__ lin1W, const float* __restrict__ lin1b,
                            const float* __restrict__ lin2W, const float* __restrict__ lin2b,
                            float* __restrict__ outp) {
    int gid  = blockIdx.x * blockDim.x + threadIdx.x;
    int g    = gid >> 5;
    int lane = gid & 31;
    if (g >= N_GRAPHS) return;
    float rc = 1.0f / fmaxf(g_cnt[g], 1.0f);
    float acc = 0.f;
#pragma unroll
    for (int k = 0; k < 64; k++)
        acc += g_pool[(size_t)g * 64 + k] * lin1W[k * 32 + lane];
    acc = fmaxf(fmaf(acc, rc, lin1b[lane]), 0.f);
    float part = acc * lin2W[lane];
#pragma unroll
    for (int off = 16; off; off >>= 1)
        part += __shfl_down_sync(0xffffffffu, part, off);
    if (lane == 0) outp[g] = part + lin2b[0];
}

// ---------------------------------------------------------------------------
extern "C" void kernel_launch(void* const* d_in, const int* in_sizes, int n_in,
                              void* d_out, int out_size) {
    const float* x     = (const float*)d_in[0];
    const int*   e_idx = (const int*)  d_in[1];
    const int*   src   = e_idx;
    const int*   dst   = e_idx + N_EDGES;
    const int*   b     = (const int*)  d_in[2];
    const float* w0    = (const float*)d_in[3];
    const float* b0    = (const float*)d_in[4];
    const float* convW = (const float*)d_in[5];
    const float* convB = (const float*)d_in[6];
    const float* skipW = (const float*)d_in[7];
    const float* skipB = (const float*)d_in[8];
    const float* lin1W = (const float*)d_in[9];
    const float* lin1b = (const float*)d_in[10];
    const float* lin2W = (const float*)d_in[11];
    const float* lin2b = (const float*)d_in[12];
    float* out = (float*)d_out;

    float *deg, *pool, *cnt;
    cudaGetSymbolAddress((void**)&deg,  g_deg);
    cudaGetSymbolAddress((void**)&pool, g_pool);
    cudaGetSymbolAddress((void**)&cnt,  g_cnt);

    const int SMEM0 = (128 * 64 + 128 * 129) * 4;   // 98816 B
    const int SMEMD = (2 * 64 * 64 + 128 * 65) * 4; // 66048 B
    cudaFuncSetAttribute(gemm0_kernel, cudaFuncAttributeMaxDynamicSharedMemorySize, SMEM0);
    cudaFuncSetAttribute(gemm_dual_kernel<0>, cudaFuncAttributeMaxDynamicSharedMemorySize, SMEMD);
    cudaFuncSetAttribute(gemm_dual_kernel<1>, cudaFuncAttributeMaxDynamicSharedMemorySize, SMEMD);

    const int NB_NODE  = (N_NODES + 255) / 256;
    const int NB_GEMM  = (N_NODES + 127) / 128;        // 782
    const int NB_EDGEV = (N_EDGES * 8 + 255) / 256;    // 50000
    const int NB_HV    = (N_NODES * 16 + 255) / 256;   // 6250
    const int NB_EDGE  = (N_EDGES + 255) / 256;

    // degree + normalization (coef machinery eliminated: normalization is
    // folded into the GEMM epilogue [·dinv] and the consumer [·dinv + bias])
    zero_kernel<<<NB_NODE, 256>>>(deg, N_NODES);
    deg_kernel<<<NB_EDGE, 256>>>(dst);
    dinv_kernel<<<NB_NODE, 256>>>();

    // layer 0: agg0 = (x@w0)*dinv (self) + scatter of pre-scaled messages
    gemm0_kernel<<<NB_GEMM, 256, SMEM0>>>(x, w0);
    edge_kernel<<<NB_EDGEV, 256>>>(src, dst);

    // layer 1: x1 = relu(agg0*dinv + b0); conv+skip fused GEMM, then edge pass
    gemm_dual_kernel<0><<<NB_GEMM, 256, SMEMD>>>(convW, b0, skipW, skipB);
    edge_kernel<<<NB_EDGEV, 256>>>(src, dst);

    // layer 2: x2 = relu(agg1*dinv + convB[0]) + hs1; fused GEMM, edge pass
    gemm_dual_kernel<1><<<NB_GEMM, 256, SMEMD>>>(convW + 64 * 64, convB,
                                                 skipW + 64 * 64, skipB + 64);
    edge_kernel<<<NB_EDGEV, 256>>>(src, dst);

    // global mean pool (h = relu(agg2*dinv + convB[1]) + hs2) + MLP head
    zero_kernel<<<(N_GRAPHS * 64 + 255) / 256, 256>>>(pool, N_GRAPHS * 64);
    zero_kernel<<<(N_GRAPHS + 255) / 256, 256>>>(cnt, N_GRAPHS);
    pool_kernel<<<NB_HV, 256>>>(b, convB + 64);
    head_kernel<<<(N_GRAPHS * 32 + 255) / 256, 256>>>(lin1W, lin1b, lin2W, lin2b, out);
}

// round 10
// speedup vs baseline: 1.0925x; 1.0510x over previous
#include <cuda_runtime.h>
#include <cuda_bf16.h>
#include <cstddef>

#define N_NODES 100000
#define N_EDGES 1600000
#define N_FEAT  128
#define H_CH    64
#define N_GRAPHS 4096

// ---------------------------------------------------------------------------
// Scratch (device globals; no allocation allowed)
// ---------------------------------------------------------------------------
__device__ float g_deg [N_NODES];
__device__ float g_dinv[N_NODES];
__device__ float g_hw  [(size_t)N_NODES * H_CH];   // pre-scaled message: (h@W)*dinv[n]
__device__ float g_agg [(size_t)N_NODES * H_CH];   // pre-scale-domain accumulator
__device__ float g_hs  [(size_t)N_NODES * H_CH];   // skip-path result
__device__ float g_pool[(size_t)N_GRAPHS * H_CH];
__device__ float g_cnt [N_GRAPHS];

// ---------------------------------------------------------------------------
// Small utility kernels
// ---------------------------------------------------------------------------
__global__ void zero_kernel(float* __restrict__ p, int n) {
    int i = blockIdx.x * blockDim.x + threadIdx.x;
    if (i < n) p[i] = 0.f;
}

__global__ void deg_kernel(const int* __restrict__ dst) {
    int i = blockIdx.x * blockDim.x + threadIdx.x;
    if (i < N_EDGES) atomicAdd(&g_deg[dst[i]], 1.0f);
}

__global__ void dinv_kernel() {
    int i = blockIdx.x * blockDim.x + threadIdx.x;
    if (i < N_NODES) g_dinv[i] = rsqrtf(g_deg[i] + 1.0f);
}

// ---------------------------------------------------------------------------
// Layer-0 GEMM:  raw[N,64] = X[N,128] @ W[128,64]
// Epilogue (pre-scale domain): hwS = raw * dinv[n];  agg = hwS  (self-term).
// 64 nodes/block, K staged in two 64-chunks (smem 48.3KB -> 4 blocks/SM).
// 256 threads: 8 warps x 8 out-cols; lane covers nodes {lane, lane+32}.
// ---------------------------------------------------------------------------
__global__ void __launch_bounds__(256)
gemm0_kernel(const float* __restrict__ X, const float* __restrict__ W) {
    const int K = 128;
    const int KC = 64;                 // K-chunk
    extern __shared__ float sm[];
    float* Ws = sm;                    // 128*64 = 32KB
    float* Xs = sm + K * 64;           // 64*65  = 16.64KB (one chunk)

    const int tid = threadIdx.x;
    const int n0  = blockIdx.x * 64;

    for (int i = tid; i < K * 64 / 4; i += 256)
        *(float4*)&Ws[i * 4] = *(const float4*)&W[i * 4];

    const int lane = tid & 31;
    const int warp = tid >> 5;
    const int og   = warp * 8;

    float acc[2][8];
#pragma unroll
    for (int r = 0; r < 2; r++)
#pragma unroll
        for (int j = 0; j < 8; j++) acc[r][j] = 0.f;

    const float* xr0 = &Xs[(lane +  0) * (KC + 1)];
    const float* xr1 = &Xs[(lane + 32) * (KC + 1)];

#pragma unroll
    for (int ck = 0; ck < 2; ck++) {
        __syncthreads();               // previous chunk's compute done
        for (int i = tid; i < 64 * KC / 4; i += 256) {
            int r = i / (KC / 4), c4 = i - r * (KC / 4);
            int n = n0 + r;
            float4 xv = make_float4(0.f, 0.f, 0.f, 0.f);
            if (n < N_NODES) xv = *(const float4*)&X[(size_t)n * K + ck * KC + c4 * 4];
            float* xp = &Xs[r * (KC + 1) + c4 * 4];
            xp[0] = xv.x; xp[1] = xv.y; xp[2] = xv.z; xp[3] = xv.w;
        }
        __syncthreads();

#pragma unroll 4
        for (int k = 0; k < KC; k++) {
            const float4 wa = *(const float4*)&Ws[(ck * KC + k) * 64 + og];
            const float4 wb = *(const float4*)&Ws[(ck * KC + k) * 64 + og + 4];
            float xv;
#define DO_ROW(r, xp)                                                        \
            xv = xp[k];                                                      \
            acc[r][0] += xv * wa.x; acc[r][1] += xv * wa.y;                  \
            acc[r][2] += xv * wa.z; acc[r][3] += xv * wa.w;                  \
            acc[r][4] += xv * wb.x; acc[r][5] += xv * wb.y;                  \
            acc[r][6] += xv * wb.z; acc[r][7] += xv * wb.w;
            DO_ROW(0, xr0) DO_ROW(1, xr1)
#undef DO_ROW
        }
    }

#pragma unroll
    for (int r = 0; r < 2; r++) {
        int n = n0 + lane + 32 * r;
        if (n >= N_NODES) continue;
        float dn = g_dinv[n];
        float* op = g_hw  + (size_t)n * 64 + og;
        float* ap = g_agg + (size_t)n * 64 + og;
        float4 o0 = make_float4(acc[r][0] * dn, acc[r][1] * dn, acc[r][2] * dn, acc[r][3] * dn);
        float4 o1 = make_float4(acc[r][4] * dn, acc[r][5] * dn, acc[r][6] * dn, acc[r][7] * dn);
        *(float4*)op       = o0;
        *(float4*)(op + 4) = o1;
        *(float4*)ap       = o0;        // self-term init (pre-scale domain)
        *(float4*)(ap + 4) = o1;
    }
}

// ---------------------------------------------------------------------------
// Fused dual GEMM for layers 1.. : input h computed on the fly:
//   MODE 0:  x = relu(agg*dinv[n] + bias_prev)
//   MODE 1:  x = relu(agg*dinv[n] + bias_prev) + hs
// conv: raw = x @ Wc;  hwS = raw*dinv;  agg = hwS     (overwrites agg)
// skip: g_hs = x @ Wsk + bs                           (overwrites hs)
// 64 nodes/block (smem 49.4KB, 32 accs -> 3-4 blocks/SM).
// Safe: each block reads exactly the rows it later writes (disjoint blocks).
// ---------------------------------------------------------------------------
template <int MODE>
__global__ void __launch_bounds__(256)
gemm_dual_kernel(const float* __restrict__ Wc, const float* __restrict__ bias_prev,
                 const float* __restrict__ Wsk, const float* __restrict__ bs) {
    const int K = 64;
    extern __shared__ float sm[];
    float* Wcs = sm;                    // 64*64 = 16KB
    float* Wss = sm + K * 64;           // 64*64 = 16KB
    float* Xs  = sm + 2 * K * 64;       // 64*65 = 16.64KB

    const int tid = threadIdx.x;
    const int n0  = blockIdx.x * 64;

    for (int i = tid; i < K * 64 / 4; i += 256) {
        *(float4*)&Wcs[i * 4] = *(const float4*)&Wc[i * 4];
        *(float4*)&Wss[i * 4] = *(const float4*)&Wsk[i * 4];
    }
    for (int i = tid; i < 64 * K / 4; i += 256) {
        int r = i / (K / 4), c4 = i - r * (K / 4);
        int n = n0 + r;
        float4 xv = make_float4(0.f, 0.f, 0.f, 0.f);
        if (n < N_NODES) {
            float dn = g_dinv[n];
            float4 bb = *(const float4*)&bias_prev[c4 * 4];
            float4 a = *(const float4*)&g_agg[(size_t)n * K + c4 * 4];
            xv = make_float4(fmaxf(fmaf(a.x, dn, bb.x), 0.f),
                             fmaxf(fmaf(a.y, dn, bb.y), 0.f),
                             fmaxf(fmaf(a.z, dn, bb.z), 0.f),
                             fmaxf(fmaf(a.w, dn, bb.w), 0.f));
            if (MODE == 1) {
                float4 s = *(const float4*)&g_hs[(size_t)n * K + c4 * 4];
                xv.x += s.x; xv.y += s.y; xv.z += s.z; xv.w += s.w;
            }
        }
        float* xp = &Xs[r * (K + 1) + c4 * 4];
        xp[0] = xv.x; xp[1] = xv.y; xp[2] = xv.z; xp[3] = xv.w;
    }
    __syncthreads();

    const int lane = tid & 31;
    const int warp = tid >> 5;
    const int og   = warp * 8;

    float accC[2][8], accS[2][8];
#pragma unroll
    for (int r = 0; r < 2; r++)
#pragma unroll
        for (int j = 0; j < 8; j++) { accC[r][j] = 0.f; accS[r][j] = 0.f; }

    const float* xr0 = &Xs[(lane +  0) * (K + 1)];
    const float* xr1 = &Xs[(lane + 32) * (K + 1)];

#pragma unroll 2
    for (int k = 0; k < K; k++) {
        const float4 ca = *(const float4*)&Wcs[k * 64 + og];
        const float4 cb = *(const float4*)&Wcs[k * 64 + og + 4];
        const float4 sa = *(const float4*)&Wss[k * 64 + og];
        const float4 sb = *(const float4*)&Wss[k * 64 + og + 4];
        float xv;
#define DO_ROW(r, xp)                                                          \
        xv = xp[k];                                                            \
        accC[r][0] += xv * ca.x; accC[r][1] += xv * ca.y;                      \
        accC[r][2] += xv * ca.z; accC[r][3] += xv * ca.w;                      \
        accC[r][4] += xv * cb.x; accC[r][5] += xv * cb.y;                      \
        accC[r][6] += xv * cb.z; accC[r][7] += xv * cb.w;                      \
        accS[r][0] += xv * sa.x; accS[r][1] += xv * sa.y;                      \
        accS[r][2] += xv * sa.z; accS[r][3] += xv * sa.w;                      \
        accS[r][4] += xv * sb.x; accS[r][5] += xv * sb.y;                      \
        accS[r][6] += xv * sb.z; accS[r][7] += xv * sb.w;
        DO_ROW(0, xr0) DO_ROW(1, xr1)
#undef DO_ROW
    }

    const float4 bsa = *(const float4*)&bs[og];
    const float4 bsb = *(const float4*)&bs[og + 4];

#pragma unroll
    for (int r = 0; r < 2; r++) {
        int n = n0 + lane + 32 * r;
        if (n >= N_NODES) continue;
        float dn = g_dinv[n];
        float* op = g_hw  + (size_t)n * 64 + og;
        float* ap = g_agg + (size_t)n * 64 + og;
        float* sp = g_hs  + (size_t)n * 64 + og;
        float4 o0 = make_float4(accC[r][0] * dn, accC[r][1] * dn, accC[r][2] * dn, accC[r][3] * dn);
        float4 o1 = make_float4(accC[r][4] * dn, accC[r][5] * dn, accC[r][6] * dn, accC[r][7] * dn);
        *(float4*)op       = o0;
        *(float4*)(op + 4) = o1;
        *(float4*)ap       = o0;        // self-term init (pre-scale domain)
        *(float4*)(ap + 4) = o1;
        *(float4*)sp       = make_float4(accS[r][0] + bsa.x, accS[r][1] + bsa.y,
                                         accS[r][2] + bsa.z, accS[r][3] + bsa.w);
        *(float4*)(sp + 4) = make_float4(accS[r][4] + bsb.x, accS[r][5] + bsb.y,
                                         accS[r][6] + bsb.z, accS[r][7] + bsb.w);
    }
}

// ---------------------------------------------------------------------------
// Edge aggregation (pre-scale domain): agg[dst] += hwS[src]
// 8 threads per edge; each handles two float4 chunks.
// ---------------------------------------------------------------------------
__global__ void __launch_bounds__(256) edge_kernel(const int* __restrict__ src,
                                                   const int* __restrict__ dst) {
    int gid = blockIdx.x * blockDim.x + threadIdx.x;
    int e = gid >> 3;
    if (e >= N_EDGES) return;
    const int s = __ldg(&src[e]);
    const int d = __ldg(&dst[e]);
    const int q = (gid & 7) << 2;              // 0,4,...,28
    const float* hp = &g_hw[(size_t)s * 64 + q];
    float* ap = &g_agg[(size_t)d * 64 + q];
    float4 v0 = __ldg((const float4*)hp);
    float4 v1 = __ldg((const float4*)(hp + 32));
    asm volatile("red.global.add.v4.f32 [%0], {%1, %2, %3, %4};"
                 :: "l"(ap), "f"(v0.x), "f"(v0.y), "f"(v0.z), "f"(v0.w) : "memory");
    asm volatile("red.global.add.v4.f32 [%0], {%1, %2, %3, %4};"
                 :: "l"(ap + 32), "f"(v1.x), "f"(v1.y), "f"(v1.z), "f"(v1.w) : "memory");
}

// global mean-pool accumulation; h = relu(agg*dinv + bias2) + hs on the fly
__global__ void pool_kernel(const int* __restrict__ b, const float* __restrict__ bias2) {
    int gid = blockIdx.x * blockDim.x + threadIdx.x;
    int n = gid >> 4;
    if (n >= N_NODES) return;
    int q = (gid & 15) << 2;
    int g = __ldg(&b[n]);
    float dn = __ldg(&g_dinv[n]);
    float4 bb = *(const float4*)&bias2[q];
    float4 a = __ldg((const float4*)&g_agg[(size_t)n * 64 + q]);
    float4 s = __ldg((const float4*)&g_hs[(size_t)n * 64 + q]);
    float4 v = make_float4(fmaxf(fmaf(a.x, dn, bb.x), 0.f) + s.x,
                           fmaxf(fmaf(a.y, dn, bb.y), 0.f) + s.y,
                           fmaxf(fmaf(a.z, dn, bb.z), 0.f) + s.z,
                           fmaxf(fmaf(a.w, dn, bb.w), 0.f) + s.w);
    float* p = &g_pool[(size_t)g * 64 + q];
    asm volatile("red.global.add.v4.f32 [%0], {%1, %2, %3, %4};"
                 :: "l"(p), "f"(v.x), "f"(v.y), "f"(v.z), "f"(v.w) : "memory");
    if (q == 0) atomicAdd(&g_cnt[g], 1.0f);
}

// MLP head: one warp per graph
__global__ void head_kernel(const float* __restrict__ lin1W, const float* __restrict__ lin1b,
                            const float* __restrict__ lin2W, const float* __restrict__ lin2b,
                            float* __restrict__ outp) {
    int gid  = blockIdx.x * blockDim.x + threadIdx.x;
    int g    = gid >> 5;
    int lane = gid & 31;
    if (g >= N_GRAPHS) return;
    float rc = 1.0f / fmaxf(g_cnt[g], 1.0f);
    float acc = 0.f;
#pragma unroll
    for (int k = 0; k < 64; k++)
        acc += g_pool[(size_t)g * 64 + k] * lin1W[k * 32 + lane];
    acc = fmaxf(fmaf(acc, rc, lin1b[lane]), 0.f);
    float part = acc * lin2W[lane];
#pragma unroll
    for (int off = 16; off; off >>= 1)
        part += __shfl_down_sync(0xffffffffu, part, off);
    if (lane == 0) outp[g] = part + lin2b[0];
}

// ---------------------------------------------------------------------------
extern "C" void kernel_launch(void* const* d_in, const int* in_sizes, int n_in,
                              void* d_out, int out_size) {
    const float* x     = (const float*)d_in[0];
    const int*   e_idx = (const int*)  d_in[1];
    const int*   src   = e_idx;
    const int*   dst   = e_idx + N_EDGES;
    const int*   b     = (const int*)  d_in[2];
    const float* w0    = (const float*)d_in[3];
    const float* b0    = (const float*)d_in[4];
    const float* convW = (const float*)d_in[5];
    const float* convB = (const float*)d_in[6];
    const float* skipW = (const float*)d_in[7];
    const float* skipB = (const float*)d_in[8];
    const float* lin1W = (const float*)d_in[9];
    const float* lin1b = (const float*)d_in[10];
    const float* lin2W = (const float*)d_in[11];
    const float* lin2b = (const float*)d_in[12];
    float* out = (float*)d_out;

    float *deg, *pool, *cnt;
    cudaGetSymbolAddress((void**)&deg,  g_deg);
    cudaGetSymbolAddress((void**)&pool, g_pool);
    cudaGetSymbolAddress((void**)&cnt,  g_cnt);

    const int SMEM0 = (128 * 64 + 64 * 65) * 4;     // 49408 B
    const int SMEMD = (2 * 64 * 64 + 64 * 65) * 4;  // 49408 B
    cudaFuncSetAttribute(gemm0_kernel, cudaFuncAttributeMaxDynamicSharedMemorySize, SMEM0);
    cudaFuncSetAttribute(gemm_dual_kernel<0>, cudaFuncAttributeMaxDynamicSharedMemorySize, SMEMD);
    cudaFuncSetAttribute(gemm_dual_kernel<1>, cudaFuncAttributeMaxDynamicSharedMemorySize, SMEMD);

    const int NB_NODE  = (N_NODES + 255) / 256;
    const int NB_GEMM  = (N_NODES + 63) / 64;          // 1563
    const int NB_EDGEV = (N_EDGES * 8 + 255) / 256;    // 50000
    const int NB_HV    = (N_NODES * 16 + 255) / 256;   // 6250
    const int NB_EDGE  = (N_EDGES + 255) / 256;

    // degree + normalization
    zero_kernel<<<NB_NODE, 256>>>(deg, N_NODES);
    deg_kernel<<<NB_EDGE, 256>>>(dst);
    dinv_kernel<<<NB_NODE, 256>>>();

    // layer 0: agg0 = (x@w0)*dinv (self) + scatter of pre-scaled messages
    gemm0_kernel<<<NB_GEMM, 256, SMEM0>>>(x, w0);
    edge_kernel<<<NB_EDGEV, 256>>>(src, dst);

    // layer 1: x1 = relu(agg0*dinv + b0); conv+skip fused GEMM, then edge pass
    gemm_dual_kernel<0><<<NB_GEMM, 256, SMEMD>>>(convW, b0, skipW, skipB);
    edge_kernel<<<NB_EDGEV, 256>>>(src, dst);

    // layer 2: x2 = relu(agg1*dinv + convB[0]) + hs1; fused GEMM, edge pass
    gemm_dual_kernel<1><<<NB_GEMM, 256, SMEMD>>>(convW + 64 * 64, convB,
                                                 skipW + 64 * 64, skipB + 64);
    edge_kernel<<<NB_EDGEV, 256>>>(src, dst);

    // global mean pool (h = relu(agg2*dinv + convB[1]) + hs2) + MLP head
    zero_kernel<<<(N_GRAPHS * 64 + 255) / 256, 256>>>(pool, N_GRAPHS * 64);
    zero_kernel<<<(N_GRAPHS + 255) / 256, 256>>>(cnt, N_GRAPHS);
    pool_kernel<<<NB_HV, 256>>>(b, convB + 64);
    head_kernel<<<(N_GRAPHS * 32 + 255) / 256, 256>>>(lin1W, lin1b, lin2W, lin2b, out);
}